// round 1
// baseline (speedup 1.0000x reference)
#include <cuda_runtime.h>
#include <cuda_bf16.h>
#include <math.h>

// Problem dims (fixed by the dataset)
#define Nn 64
#define Cc 8
#define Tt 300
#define Vv 17
#define Mm 12
#define SLICES (Nn*Cc*Tt)          // 153600 (n,c,t) slices of V*M=204 floats
#define TOTAL   (Nn*Cc*Tt*Vv*Mm)   // 31,334,400
#define TOTAL4  (TOTAL/4)          // 7,833,600
#define EPSF 1e-6f
#define TAUF 0.35f

// Scratch (device globals — no allocation allowed)
__device__ float  g_A[Nn*Mm*Mm];          // per-sample 12x12 adjacency
__device__ float4 g_delta4[SLICES*3];     // 12 floats per slice, as 3 float4

// ---------------------------------------------------------------------------
// Kernel A: per-sample stats (pos, s) + full graph construction -> g_A
// one block per n, 256 threads
// ---------------------------------------------------------------------------
__global__ __launch_bounds__(256) void stats_kernel(
    const float* __restrict__ x,
    const float* __restrict__ alpha_logits)
{
    const int n   = blockIdx.x;
    const int tid = threadIdx.x;
    const float* xn = x + (size_t)n * Cc * Tt * Vv * Mm;

    __shared__ float red[256];
    __shared__ float s[12];
    __shared__ float p[12];
    __shared__ float pos[3][12];
    __shared__ float alpha[4];
    __shared__ float wsh;

    // ---- s[m] = mean over (t,v) of x[n,3,t,v,m] : coalesced, fixed m/thread
    float acc = 0.f;
    if (tid < 252) {
        const int m = tid % 12, col = tid / 12;           // 21 columns
        const float* b = xn + 3 * Tt * Vv * Mm;
        for (int r = col; r < Tt * Vv; r += 21)
            acc += b[r * 12 + m];
    }
    red[tid] = acc;
    __syncthreads();
    if (tid < 12) {
        float t = 0.f;
        for (int c = 0; c < 21; c++) t += red[c * 12 + tid];
        s[tid] = t * (1.0f / (Tt * Vv));
    }

    // ---- pos[d][m] = mean over t of 0.5*(x[n,d,t,11,m] + x[n,d,t,12,m])
    float pa0 = 0.f, pa1 = 0.f, pa2 = 0.f;
    if (tid < 240) {
        const int sub = tid % 24;     // v*12 + m, v in {0,1} -> joints 11,12
        const int tg  = tid / 24;     // 0..9
        const float* b0 = xn + 0 * Tt * Vv * Mm + 132 + sub;
        const float* b1 = xn + 1 * Tt * Vv * Mm + 132 + sub;
        const float* b2 = xn + 2 * Tt * Vv * Mm + 132 + sub;
        for (int t = tg; t < Tt; t += 10) {
            const int o = t * (Vv * Mm);
            pa0 += b0[o]; pa1 += b1[o]; pa2 += b2[o];
        }
    }
    for (int d = 0; d < 3; d++) {
        __syncthreads();
        red[tid] = (d == 0) ? pa0 : (d == 1) ? pa1 : pa2;
        __syncthreads();
        if (tid < 12) {
            float t = 0.f;
            for (int tg = 0; tg < 10; tg++)
                t += red[tg * 24 + tid] + red[tg * 24 + tid + 12];
            pos[d][tid] = t * (0.5f / Tt);
        }
    }
    __syncthreads();

    // ---- tiny serial work: alpha softmax, ball softmax, w
    if (tid == 0) {
        float mx = alpha_logits[0];
        for (int k = 1; k < 4; k++) mx = fmaxf(mx, alpha_logits[k]);
        float e[4], se = 0.f;
        for (int k = 0; k < 4; k++) { e[k] = expf(alpha_logits[k] - mx); se += e[k]; }
        for (int k = 0; k < 4; k++) alpha[k] = e[k] / se;

        float smax = -1e30f;
        for (int m = 0; m < 12; m++) smax = fmaxf(smax, s[m] * (1.0f / TAUF));
        float ps = 0.f;
        for (int m = 0; m < 12; m++) { p[m] = expf(s[m] * (1.0f / TAUF) - smax); ps += p[m]; }
        float pmax = 0.f;
        for (int m = 0; m < 12; m++) { p[m] /= ps; pmax = fmaxf(pmax, p[m]); }

        float w = (pmax - 1.0f / 12.0f) / (1.0f - 1.0f / 12.0f + EPSF);
        wsh = fminf(fmaxf(w, 0.0f), 1.0f);
    }
    __syncthreads();

    // ---- per-row graph build (12 threads, one per row i)
    if (tid < 12) {
        const int i = tid;
        float dist[12];
        for (int j = 0; j < 12; j++) {
            float dx = pos[0][i] - pos[0][j];
            float dy = pos[1][i] - pos[1][j];
            float dz = pos[2][i] - pos[2][j];
            dist[j] = dx * dx + dy * dy + dz * dz;   // ordering == euclid
        }
        // 5-NN selection order; ties -> lowest index (matches jax top_k)
        int rank[12];
        bool used[12];
        for (int j = 0; j < 12; j++) { rank[j] = 9; used[j] = false; }
        for (int r = 0; r < 5; r++) {
            float best = 3.4e38f; int bj = 0;
            for (int j = 0; j < 12; j++)
                if (!used[j] && dist[j] < best) { best = dist[j]; bj = j; }
            used[bj] = true; rank[bj] = r;
        }
        // sym_norm(A_k) = A_k * rsqrt(k+1+eps)^2 ; row sums are exactly k+1
        float invk[4];
        for (int kidx = 0; kidx < 4; kidx++) {
            float ds = rsqrtf((float)(kidx + 3) + EPSF);   // k+1 = kidx+3
            invk[kidx] = alpha[kidx] * ds * ds;
        }
        const float diagsum = invk[0] + invk[1] + invk[2] + invk[3];
        float rankw[5];
        rankw[0] = diagsum;                       // rank<k for all k in {2..5}
        rankw[1] = diagsum;
        rankw[2] = invk[1] + invk[2] + invk[3];   // k in {3,4,5}
        rankw[3] = invk[2] + invk[3];             // k in {4,5}
        rankw[4] = invk[3];                       // k = 5

        const float w    = wsh;
        const float disb_i = rsqrtf(12.0f * p[i] + 2.0f + EPSF);
        float* Arow = g_A + (n * 144 + i * 12);
        for (int j = 0; j < 12; j++) {
            float aknn = (rank[j] < 5 ? rankw[rank[j]] : 0.0f)
                       + (i == j ? diagsum : 0.0f);
            float disb_j = rsqrtf(12.0f * p[j] + 2.0f + EPSF);
            float aball = disb_i * disb_j * (p[i] + p[j] + (i == j ? 1.0f : 0.0f));
            Arow[j] = w * aball + (1.0f - w) * aknn;
        }
    }
}

// ---------------------------------------------------------------------------
// Kernel B: delta[n,c,t,m] = coef * (sum_j A[n,m,j]*root[j] - root[m])
// ---------------------------------------------------------------------------
__global__ __launch_bounds__(256) void delta_kernel(
    const float* __restrict__ x,
    const float* __restrict__ lambda_fuse,
    const float* __restrict__ tag_gate)
{
    const int gid = blockIdx.x * blockDim.x + threadIdx.x;
    if (gid >= SLICES * Mm) return;
    const float coef = tanhf(tag_gate[0]) * lambda_fuse[0];

    const int m     = gid % 12;
    const int slice = gid / 12;
    const int n     = slice / (Cc * Tt);

    const float* xb = x + (size_t)slice * (Vv * Mm) + 11 * Mm;   // joints 11,12
    const float* Ar = g_A + n * 144 + m * 12;

    float agg = 0.f, rm = 0.f;
#pragma unroll
    for (int j = 0; j < 12; j++) {
        float r = 0.5f * (xb[j] + xb[12 + j]);
        agg = fmaf(Ar[j], r, agg);
        if (j == m) rm = r;
    }
    reinterpret_cast<float*>(g_delta4)[gid] = coef * (agg - rm);
}

// ---------------------------------------------------------------------------
// Kernel C: streaming out = x + delta (float4, fully coalesced)
// 204 floats/slice = 51 float4; m%12 never wraps inside an aligned float4.
// ---------------------------------------------------------------------------
__global__ __launch_bounds__(256) void add_kernel(
    const float4* __restrict__ x4, float4* __restrict__ out4)
{
    const int i = blockIdx.x * blockDim.x + threadIdx.x;
    if (i >= TOTAL4) return;
    const int slice = i / 51;
    const int r     = i - slice * 51;
    const float4 d  = g_delta4[slice * 3 + (r % 3)];
    float4 xv = x4[i];
    xv.x += d.x; xv.y += d.y; xv.z += d.z; xv.w += d.w;
    out4[i] = xv;
}

// ---------------------------------------------------------------------------
extern "C" void kernel_launch(void* const* d_in, const int* in_sizes, int n_in,
                              void* d_out, int out_size)
{
    const float* x            = (const float*)d_in[0];
    const float* alpha_logits = (const float*)d_in[1];
    const float* lambda_fuse  = (const float*)d_in[2];
    const float* tag_gate     = (const float*)d_in[3];
    float* out = (float*)d_out;

    stats_kernel<<<Nn, 256>>>(x, alpha_logits);

    const int nB = (SLICES * Mm + 255) / 256;
    delta_kernel<<<nB, 256>>>(x, lambda_fuse, tag_gate);

    const int nC = (TOTAL4 + 255) / 256;
    add_kernel<<<nC, 256>>>((const float4*)x, (float4*)out);
}

// round 2
// speedup vs baseline: 1.3415x; 1.3415x over previous
#include <cuda_runtime.h>
#include <cuda_bf16.h>
#include <math.h>

// Problem dims (fixed by the dataset)
#define Nn 64
#define Cc 8
#define Tt 300
#define Vv 17
#define Mm 12
#define SLICES (Nn*Cc*Tt)          // 153600 (n,c,t) slices of V*M=204 floats
#define TOTAL   (Nn*Cc*Tt*Vv*Mm)   // 31,334,400
#define EPSF 1e-6f
#define TAUF 0.35f

#define NCHUNK 10                  // T split into 10 chunks of 30
#define SL 16                      // slices per block in fused kernel

// Scratch (device globals — no allocation allowed)
__device__ float g_A[Nn*Mm*Mm];               // per-sample 12x12 adjacency
__device__ float g_part[Nn*NCHUNK*48];        // partial sums: 12 s + 36 pos per (n,chunk)

// ---------------------------------------------------------------------------
// Kernel 1: partial reductions. grid = 64*10 blocks, 256 threads.
// Each block handles one (n, T-chunk of 30): s-sums (channel 3, all v) and
// pos-sums (channels 0..2, joints 11/12).
// ---------------------------------------------------------------------------
__global__ __launch_bounds__(256) void stats1_kernel(const float* __restrict__ x)
{
    const int b   = blockIdx.x;
    const int n   = b / NCHUNK, ch = b % NCHUNK;
    const int tid = threadIdx.x;
    const float* xn = x + (size_t)n * Cc * Tt * Vv * Mm;

    __shared__ float red[256];

    // ---- s partial: sum over t in chunk (30), v (17) of x[n,3,t,v,m]
    float acc = 0.f;
    if (tid < 252) {
        const int m = tid % 12, col = tid / 12;               // 21 columns
        const float* bp = xn + 3 * Tt * Vv * Mm + ch * 30 * 204;
        for (int r = col; r < 30 * 17; r += 21)
            acc += bp[r * 12 + m];
    }
    red[tid] = acc;
    __syncthreads();
    if (tid < 12) {
        float t = 0.f;
        for (int c = 0; c < 21; c++) t += red[c * 12 + tid];
        g_part[b * 48 + tid] = t;
    }

    // ---- pos partials: sum over t in chunk of x[n,d,t,{11,12},m]
    float pa[3] = {0.f, 0.f, 0.f};
    if (tid < 240) {
        const int sub = tid % 24;      // v*12+m for joints 11,12
        const int tg  = tid / 24;      // 0..9
#pragma unroll
        for (int d = 0; d < 3; d++) {
            const float* bp = xn + d * Tt * Vv * Mm + 132 + sub;
            float a = 0.f;
            for (int t = ch * 30 + tg; t < ch * 30 + 30; t += 10)
                a += bp[t * 204];
            pa[d] = a;
        }
    }
#pragma unroll
    for (int d = 0; d < 3; d++) {
        __syncthreads();
        red[tid] = pa[d];
        __syncthreads();
        if (tid < 12) {
            float t = 0.f;
            for (int tg = 0; tg < 10; tg++)
                t += red[tg * 24 + tid] + red[tg * 24 + tid + 12];
            g_part[b * 48 + 12 + d * 12 + tid] = t;
        }
    }
}

// ---------------------------------------------------------------------------
// Kernel 2: reduce partials + build A. grid = 64 blocks, 64 threads.
// ---------------------------------------------------------------------------
__global__ __launch_bounds__(64) void graph_kernel(const float* __restrict__ alpha_logits)
{
    const int n = blockIdx.x, tid = threadIdx.x;
    __shared__ float s[12], pos[3][12], p[12], alpha[4], wsh;

    if (tid < 48) {
        float t = 0.f;
        for (int ch = 0; ch < NCHUNK; ch++)
            t += g_part[(n * NCHUNK + ch) * 48 + tid];
        if (tid < 12) s[tid] = t * (1.0f / (Tt * Vv));
        else {
            const int d = (tid - 12) / 12, m = (tid - 12) % 12;
            pos[d][m] = t * (0.5f / Tt);
        }
    }
    __syncthreads();

    if (tid == 0) {
        float mx = alpha_logits[0];
        for (int k = 1; k < 4; k++) mx = fmaxf(mx, alpha_logits[k]);
        float e[4], se = 0.f;
        for (int k = 0; k < 4; k++) { e[k] = expf(alpha_logits[k] - mx); se += e[k]; }
        for (int k = 0; k < 4; k++) alpha[k] = e[k] / se;

        float smax = -1e30f;
        for (int m = 0; m < 12; m++) smax = fmaxf(smax, s[m] * (1.0f / TAUF));
        float ps = 0.f;
        for (int m = 0; m < 12; m++) { p[m] = expf(s[m] * (1.0f / TAUF) - smax); ps += p[m]; }
        float pmax = 0.f;
        for (int m = 0; m < 12; m++) { p[m] /= ps; pmax = fmaxf(pmax, p[m]); }

        float w = (pmax - 1.0f / 12.0f) / (1.0f - 1.0f / 12.0f + EPSF);
        wsh = fminf(fmaxf(w, 0.0f), 1.0f);
    }
    __syncthreads();

    if (tid < 12) {
        const int i = tid;
        float dist[12];
        for (int j = 0; j < 12; j++) {
            float dx = pos[0][i] - pos[0][j];
            float dy = pos[1][i] - pos[1][j];
            float dz = pos[2][i] - pos[2][j];
            dist[j] = dx * dx + dy * dy + dz * dz;   // monotone in euclid
        }
        // 5-NN selection order; ties -> lowest index (matches jax top_k)
        int rank[12];
        bool used[12];
        for (int j = 0; j < 12; j++) { rank[j] = 9; used[j] = false; }
        for (int r = 0; r < 5; r++) {
            float best = 3.4e38f; int bj = 0;
            for (int j = 0; j < 12; j++)
                if (!used[j] && dist[j] < best) { best = dist[j]; bj = j; }
            used[bj] = true; rank[bj] = r;
        }
        // sym_norm(A_k) = A_k / (k+1+eps): row sums are exactly k+1
        float invk[4];
        for (int kidx = 0; kidx < 4; kidx++) {
            float ds = rsqrtf((float)(kidx + 3) + EPSF);
            invk[kidx] = alpha[kidx] * ds * ds;
        }
        const float diagsum = invk[0] + invk[1] + invk[2] + invk[3];
        float rankw[5];
        rankw[0] = diagsum;
        rankw[1] = diagsum;
        rankw[2] = invk[1] + invk[2] + invk[3];
        rankw[3] = invk[2] + invk[3];
        rankw[4] = invk[3];

        const float w = wsh;
        const float disb_i = rsqrtf(12.0f * p[i] + 2.0f + EPSF);
        float* Arow = g_A + (n * 144 + i * 12);
        for (int j = 0; j < 12; j++) {
            float aknn = (rank[j] < 5 ? rankw[rank[j]] : 0.0f)
                       + (i == j ? diagsum : 0.0f);
            float disb_j = rsqrtf(12.0f * p[j] + 2.0f + EPSF);
            float aball = disb_i * disb_j * (p[i] + p[j] + (i == j ? 1.0f : 0.0f));
            Arow[j] = w * aball + (1.0f - w) * aknn;
        }
    }
}

// ---------------------------------------------------------------------------
// Kernel 3 (fused): per block — 16 whole slices. Stage A[n] + 16x12 deltas
// in shared, then stream out = x + delta via float4.
// 204 floats/slice = 51 float4; an aligned float4 never crosses an m-wrap.
// ---------------------------------------------------------------------------
__global__ __launch_bounds__(256) void fused_kernel(
    const float* __restrict__ x, float* __restrict__ out,
    const float* __restrict__ lambda_fuse, const float* __restrict__ tag_gate)
{
    const int slice0 = blockIdx.x * SL;         // 16 | 2400 -> block within one n
    const int n      = slice0 / (Cc * Tt);
    const int tid    = threadIdx.x;

    __shared__ float A_s[144];
    __shared__ float delta_s[SL][12];           // rows 48B -> float4-aligned
    __shared__ float coef_s;

    if (tid < 144) A_s[tid] = g_A[n * 144 + tid];
    if (tid == 255) coef_s = tanhf(tag_gate[0]) * lambda_fuse[0];
    __syncthreads();

    if (tid < SL * 12) {
        const int sidx = tid / 12, m = tid % 12;
        const float* xb = x + (size_t)(slice0 + sidx) * 204 + 132;  // joints 11,12
        const float* Ar = A_s + m * 12;
        float agg = 0.f, rm = 0.f;
#pragma unroll
        for (int j = 0; j < 12; j++) {
            float r = 0.5f * (xb[j] + xb[12 + j]);
            agg = fmaf(Ar[j], r, agg);
            if (j == m) rm = r;
        }
        delta_s[sidx][m] = coef_s * (agg - rm);
    }
    __syncthreads();

    const float4* x4 = (const float4*)x   + (size_t)slice0 * 51;
    float4*       o4 = (float4*)out       + (size_t)slice0 * 51;
#pragma unroll 4
    for (int k = tid; k < SL * 51; k += 256) {
        const int sidx = k / 51, r = k - sidx * 51;
        const float4 d = *(const float4*)&delta_s[sidx][(r % 3) * 4];
        float4 xv = x4[k];
        xv.x += d.x; xv.y += d.y; xv.z += d.z; xv.w += d.w;
        o4[k] = xv;
    }
}

// ---------------------------------------------------------------------------
extern "C" void kernel_launch(void* const* d_in, const int* in_sizes, int n_in,
                              void* d_out, int out_size)
{
    const float* x            = (const float*)d_in[0];
    const float* alpha_logits = (const float*)d_in[1];
    const float* lambda_fuse  = (const float*)d_in[2];
    const float* tag_gate     = (const float*)d_in[3];
    float* out = (float*)d_out;

    stats1_kernel<<<Nn * NCHUNK, 256>>>(x);
    graph_kernel<<<Nn, 64>>>(alpha_logits);
    fused_kernel<<<SLICES / SL, 256>>>(x, out, lambda_fuse, tag_gate);
}

// round 3
// speedup vs baseline: 1.4394x; 1.0730x over previous
#include <cuda_runtime.h>
#include <cuda_bf16.h>
#include <math.h>

// Problem dims (fixed by the dataset)
#define Nn 64
#define Cc 8
#define Tt 300
#define Vv 17
#define Mm 12
#define SLICES (Nn*Cc*Tt)          // 153600 (n,c,t) slices of V*M=204 floats
#define EPSF 1e-6f
#define TAUF 0.35f

#define NCHUNK 30                  // T split into 30 chunks of 10
#define CH 10                      // t per chunk
#define SL 32                      // slices per block in fused kernel

// Scratch (device globals — no allocation allowed)
__device__ float g_A[Nn*Mm*Mm];               // per-sample 12x12 adjacency
__device__ float g_part[Nn*NCHUNK*48];        // partials: 12 s + 36 pos per (n,chunk)

// ---------------------------------------------------------------------------
// Kernel 1: partial reductions. grid = 64*30 = 1920 blocks, 256 threads.
// Each block: one (n, 10-t chunk). s-sums (channel 3, all v), pos-sums
// (channels 0..2, joints 11/12).
// ---------------------------------------------------------------------------
__global__ __launch_bounds__(256) void stats1_kernel(const float* __restrict__ x)
{
    const int b   = blockIdx.x;
    const int n   = b / NCHUNK, ch = b % NCHUNK;
    const int tid = threadIdx.x;
    const float* xn = x + (size_t)n * Cc * Tt * Vv * Mm;

    __shared__ float red[256];

    // ---- s partial: sum over 10 t, 17 v of x[n,3,t,v,m]
    // chunk slab: 10*204 = 2040 contiguous floats = 170 rows of 12
    float acc = 0.f;
    if (tid < 252) {
        const int m = tid % 12, col = tid / 12;               // 21 columns
        const float* bp = xn + 3 * Tt * Vv * Mm + ch * CH * 204;
#pragma unroll
        for (int r = col; r < CH * 17; r += 21)
            acc += bp[r * 12 + m];
    }
    red[tid] = acc;
    __syncthreads();
    if (tid < 12) {
        float t = 0.f;
#pragma unroll
        for (int c = 0; c < 21; c++) t += red[c * 12 + tid];
        g_part[b * 48 + tid] = t;
    }

    // ---- pos partials: sum over 10 t of x[n,d,t,{11,12},m]; 1 t per thread
    float pa[3] = {0.f, 0.f, 0.f};
    if (tid < 240) {
        const int sub = tid % 24;      // v*12+m for joints 11,12
        const int t   = ch * CH + tid / 24;   // tg 0..9 -> one t each
        const size_t o = (size_t)t * 204 + 132 + sub;
#pragma unroll
        for (int d = 0; d < 3; d++)
            pa[d] = xn[d * Tt * Vv * Mm + o];
    }
#pragma unroll
    for (int d = 0; d < 3; d++) {
        __syncthreads();
        red[tid] = pa[d];
        __syncthreads();
        if (tid < 12) {
            float t = 0.f;
#pragma unroll
            for (int tg = 0; tg < 10; tg++)
                t += red[tg * 24 + tid] + red[tg * 24 + tid + 12];
            g_part[b * 48 + 12 + d * 12 + tid] = t;
        }
    }
}

// ---------------------------------------------------------------------------
// Kernel 2: reduce partials + build A. grid = 64 blocks, 64 threads.
// ---------------------------------------------------------------------------
__global__ __launch_bounds__(64) void graph_kernel(const float* __restrict__ alpha_logits)
{
    const int n = blockIdx.x, tid = threadIdx.x;
    __shared__ float s[12], pos[3][12], p[12], alpha[4], wsh;

    if (tid < 48) {
        float t = 0.f;
#pragma unroll
        for (int ch = 0; ch < NCHUNK; ch++)
            t += g_part[(n * NCHUNK + ch) * 48 + tid];
        if (tid < 12) s[tid] = t * (1.0f / (Tt * Vv));
        else {
            const int d = (tid - 12) / 12, m = (tid - 12) % 12;
            pos[d][m] = t * (0.5f / Tt);
        }
    }
    __syncthreads();

    if (tid == 0) {
        float mx = alpha_logits[0];
        for (int k = 1; k < 4; k++) mx = fmaxf(mx, alpha_logits[k]);
        float e[4], se = 0.f;
        for (int k = 0; k < 4; k++) { e[k] = expf(alpha_logits[k] - mx); se += e[k]; }
        for (int k = 0; k < 4; k++) alpha[k] = e[k] / se;

        float smax = -1e30f;
        for (int m = 0; m < 12; m++) smax = fmaxf(smax, s[m] * (1.0f / TAUF));
        float ps = 0.f;
        for (int m = 0; m < 12; m++) { p[m] = expf(s[m] * (1.0f / TAUF) - smax); ps += p[m]; }
        float pmax = 0.f;
        for (int m = 0; m < 12; m++) { p[m] /= ps; pmax = fmaxf(pmax, p[m]); }

        float w = (pmax - 1.0f / 12.0f) / (1.0f - 1.0f / 12.0f + EPSF);
        wsh = fminf(fmaxf(w, 0.0f), 1.0f);
    }
    __syncthreads();

    if (tid < 12) {
        const int i = tid;
        float dist[12];
        for (int j = 0; j < 12; j++) {
            float dx = pos[0][i] - pos[0][j];
            float dy = pos[1][i] - pos[1][j];
            float dz = pos[2][i] - pos[2][j];
            dist[j] = dx * dx + dy * dy + dz * dz;   // monotone in euclid
        }
        // 5-NN selection order; ties -> lowest index (matches jax top_k)
        int rank[12];
        bool used[12];
        for (int j = 0; j < 12; j++) { rank[j] = 9; used[j] = false; }
        for (int r = 0; r < 5; r++) {
            float best = 3.4e38f; int bj = 0;
            for (int j = 0; j < 12; j++)
                if (!used[j] && dist[j] < best) { best = dist[j]; bj = j; }
            used[bj] = true; rank[bj] = r;
        }
        // sym_norm(A_k) = A_k / (k+1+eps): row sums are exactly k+1
        float invk[4];
        for (int kidx = 0; kidx < 4; kidx++) {
            float ds = rsqrtf((float)(kidx + 3) + EPSF);
            invk[kidx] = alpha[kidx] * ds * ds;
        }
        const float diagsum = invk[0] + invk[1] + invk[2] + invk[3];
        float rankw[5];
        rankw[0] = diagsum;
        rankw[1] = diagsum;
        rankw[2] = invk[1] + invk[2] + invk[3];
        rankw[3] = invk[2] + invk[3];
        rankw[4] = invk[3];

        const float w = wsh;
        const float disb_i = rsqrtf(12.0f * p[i] + 2.0f + EPSF);
        float* Arow = g_A + (n * 144 + i * 12);
        for (int j = 0; j < 12; j++) {
            float aknn = (rank[j] < 5 ? rankw[rank[j]] : 0.0f)
                       + (i == j ? diagsum : 0.0f);
            float disb_j = rsqrtf(12.0f * p[j] + 2.0f + EPSF);
            float aball = disb_i * disb_j * (p[i] + p[j] + (i == j ? 1.0f : 0.0f));
            Arow[j] = w * aball + (1.0f - w) * aknn;
        }
    }
}

// ---------------------------------------------------------------------------
// Kernel 3 (fused): per block — 32 whole slices. Stage A[n] + 32x12 deltas
// in shared, then stream out = x + delta via float4.
// 204 floats/slice = 51 float4; an aligned float4 never crosses an m-wrap.
// ---------------------------------------------------------------------------
__global__ __launch_bounds__(256) void fused_kernel(
    const float* __restrict__ x, float* __restrict__ out,
    const float* __restrict__ lambda_fuse, const float* __restrict__ tag_gate)
{
    const int slice0 = blockIdx.x * SL;         // 32 | 2400 -> block within one n
    const int n      = slice0 / (Cc * Tt);
    const int tid    = threadIdx.x;

    __shared__ float A_s[144];
    __shared__ float delta_s[SL][12];           // rows 48B -> float4-aligned
    __shared__ float coef_s;

    if (tid < 144) A_s[tid] = g_A[n * 144 + tid];
    if (tid == 0) coef_s = tanhf(tag_gate[0]) * lambda_fuse[0];
    __syncthreads();

    // delta phase: SL*12 = 384 items across 256 threads
    for (int it = tid; it < SL * 12; it += 256) {
        const int sidx = it / 12, m = it - sidx * 12;
        const float* xb = x + (size_t)(slice0 + sidx) * 204 + 132;  // joints 11,12
        const float* Ar = A_s + m * 12;
        float agg = 0.f, rm = 0.f;
#pragma unroll
        for (int j = 0; j < 12; j++) {
            float r = 0.5f * (xb[j] + xb[12 + j]);
            agg = fmaf(Ar[j], r, agg);
            if (j == m) rm = r;
        }
        delta_s[sidx][m] = coef_s * (agg - rm);
    }
    __syncthreads();

    const float4* x4 = (const float4*)x + (size_t)slice0 * 51;
    float4*       o4 = (float4*)out     + (size_t)slice0 * 51;
#pragma unroll 4
    for (int k = tid; k < SL * 51; k += 256) {
        const int sidx = k / 51, r = k - sidx * 51;
        const float4 d = *(const float4*)&delta_s[sidx][(r % 3) * 4];
        float4 xv = x4[k];
        xv.x += d.x; xv.y += d.y; xv.z += d.z; xv.w += d.w;
        o4[k] = xv;
    }
}

// ---------------------------------------------------------------------------
extern "C" void kernel_launch(void* const* d_in, const int* in_sizes, int n_in,
                              void* d_out, int out_size)
{
    const float* x            = (const float*)d_in[0];
    const float* alpha_logits = (const float*)d_in[1];
    const float* lambda_fuse  = (const float*)d_in[2];
    const float* tag_gate     = (const float*)d_in[3];
    float* out = (float*)d_out;

    stats1_kernel<<<Nn * NCHUNK, 256>>>(x);
    graph_kernel<<<Nn, 64>>>(alpha_logits);
    fused_kernel<<<SLICES / SL, 256>>>(x, out, lambda_fuse, tag_gate);
}

// round 4
// speedup vs baseline: 1.5509x; 1.0775x over previous
#include <cuda_runtime.h>
#include <cuda_bf16.h>
#include <math.h>

// Problem dims (fixed by the dataset)
#define Nn 64
#define Cc 8
#define Tt 300
#define Vv 17
#define Mm 12
#define SLICES (Nn*Cc*Tt)          // 153600 (n,c,t) slices of V*M=204 floats
#define EPSF 1e-6f
#define TAUF 0.35f

#define NCHUNK 30                  // T split into 30 chunks of 10
#define CH 10                      // t per chunk
#define SL 32                      // slices per block in fused kernel

// Scratch (device globals — no allocation allowed)
__device__ float g_A[Nn*Mm*Mm];               // per-sample 12x12 adjacency
__device__ float g_part[Nn*NCHUNK*48];        // partials: 12 s + 36 pos per (n,chunk)

// ---------------------------------------------------------------------------
// Kernel 1: partial reductions. grid = 64*30 = 1920 blocks, 256 threads.
// One (n, 10-t chunk) per block. Single __syncthreads.
// ---------------------------------------------------------------------------
__global__ __launch_bounds__(256) void stats1_kernel(const float* __restrict__ x)
{
    const int b   = blockIdx.x;
    const int n   = b / NCHUNK, ch = b % NCHUNK;
    const int tid = threadIdx.x;
    const float* xn = x + (size_t)n * Cc * Tt * Vv * Mm;

    __shared__ float sred[256];
    __shared__ float pred[3][256];

    // ---- s partial: sum over 10 t, 17 v of x[n,3,t,v,m]
    float acc = 0.f;
    if (tid < 252) {
        const int m = tid % 12, col = tid / 12;               // 21 columns
        const float* bp = xn + 3 * Tt * Vv * Mm + ch * CH * 204;
#pragma unroll
        for (int r = col; r < CH * 17; r += 21)
            acc += bp[r * 12 + m];
    }
    sred[tid] = acc;

    // ---- pos partials: one t per thread, all 3 dims at once
    if (tid < 240) {
        const int sub = tid % 24;             // v*12+m for joints 11,12
        const int t   = ch * CH + tid / 24;   // one t per thread
        const size_t o = (size_t)t * 204 + 132 + sub;
#pragma unroll
        for (int d = 0; d < 3; d++)
            pred[d][tid] = xn[(size_t)d * Tt * Vv * Mm + o];
    } else {
        pred[0][tid] = pred[1][tid] = pred[2][tid] = 0.f;
    }
    __syncthreads();

    if (tid < 12) {
        float t = 0.f;
#pragma unroll
        for (int c = 0; c < 21; c++) t += sred[c * 12 + tid];
        g_part[b * 48 + tid] = t;
    } else if (tid < 48) {
        const int d = (tid - 12) / 12, m = (tid - 12) % 12;
        float t = 0.f;
#pragma unroll
        for (int tg = 0; tg < 10; tg++)
            t += pred[d][tg * 24 + m] + pred[d][tg * 24 + m + 12];
        g_part[b * 48 + tid] = t;
    }
}

// ---------------------------------------------------------------------------
// Kernel 2: reduce partials + build A. grid = 64 blocks, 64 threads.
// ---------------------------------------------------------------------------
__global__ __launch_bounds__(64) void graph_kernel(const float* __restrict__ alpha_logits)
{
    const int n = blockIdx.x, tid = threadIdx.x;
    __shared__ float s[12], pos[3][12], p[12], alpha[4], wsh;

    if (tid < 48) {
        float t = 0.f;
#pragma unroll
        for (int ch = 0; ch < NCHUNK; ch++)
            t += g_part[(n * NCHUNK + ch) * 48 + tid];
        if (tid < 12) s[tid] = t * (1.0f / (Tt * Vv));
        else {
            const int d = (tid - 12) / 12, m = (tid - 12) % 12;
            pos[d][m] = t * (0.5f / Tt);
        }
    }
    __syncthreads();

    if (tid == 0) {
        float mx = alpha_logits[0];
        for (int k = 1; k < 4; k++) mx = fmaxf(mx, alpha_logits[k]);
        float e[4], se = 0.f;
        for (int k = 0; k < 4; k++) { e[k] = expf(alpha_logits[k] - mx); se += e[k]; }
        for (int k = 0; k < 4; k++) alpha[k] = e[k] / se;

        float smax = -1e30f;
        for (int m = 0; m < 12; m++) smax = fmaxf(smax, s[m] * (1.0f / TAUF));
        float ps = 0.f;
        for (int m = 0; m < 12; m++) { p[m] = expf(s[m] * (1.0f / TAUF) - smax); ps += p[m]; }
        float pmax = 0.f;
        for (int m = 0; m < 12; m++) { p[m] /= ps; pmax = fmaxf(pmax, p[m]); }

        float w = (pmax - 1.0f / 12.0f) / (1.0f - 1.0f / 12.0f + EPSF);
        wsh = fminf(fmaxf(w, 0.0f), 1.0f);
    }
    __syncthreads();

    if (tid < 12) {
        const int i = tid;
        float dist[12];
        for (int j = 0; j < 12; j++) {
            float dx = pos[0][i] - pos[0][j];
            float dy = pos[1][i] - pos[1][j];
            float dz = pos[2][i] - pos[2][j];
            dist[j] = dx * dx + dy * dy + dz * dz;   // monotone in euclid
        }
        // 5-NN selection order; ties -> lowest index (matches jax top_k)
        int rank[12];
        bool used[12];
        for (int j = 0; j < 12; j++) { rank[j] = 9; used[j] = false; }
        for (int r = 0; r < 5; r++) {
            float best = 3.4e38f; int bj = 0;
            for (int j = 0; j < 12; j++)
                if (!used[j] && dist[j] < best) { best = dist[j]; bj = j; }
            used[bj] = true; rank[bj] = r;
        }
        // sym_norm(A_k) = A_k / (k+1+eps): row sums are exactly k+1
        float invk[4];
        for (int kidx = 0; kidx < 4; kidx++) {
            float ds = rsqrtf((float)(kidx + 3) + EPSF);
            invk[kidx] = alpha[kidx] * ds * ds;
        }
        const float diagsum = invk[0] + invk[1] + invk[2] + invk[3];
        float rankw[5];
        rankw[0] = diagsum;
        rankw[1] = diagsum;
        rankw[2] = invk[1] + invk[2] + invk[3];
        rankw[3] = invk[2] + invk[3];
        rankw[4] = invk[3];

        const float w = wsh;
        const float disb_i = rsqrtf(12.0f * p[i] + 2.0f + EPSF);
        float* Arow = g_A + (n * 144 + i * 12);
        for (int j = 0; j < 12; j++) {
            float aknn = (rank[j] < 5 ? rankw[rank[j]] : 0.0f)
                       + (i == j ? diagsum : 0.0f);
            float disb_j = rsqrtf(12.0f * p[j] + 2.0f + EPSF);
            float aball = disb_i * disb_j * (p[i] + p[j] + (i == j ? 1.0f : 0.0f));
            Arow[j] = w * aball + (1.0f - w) * aknn;
        }
    }
}

// ---------------------------------------------------------------------------
// Kernel 3 (fused): 32 slices per block.
//  Phase 1: stage r[sidx][m] = 0.5*(x[...,11,m]+x[...,12,m]) via float4 (96 ld/blk)
//  Phase 2: delta = coef*(A·r - r) from shared, float4 LDS
//  Phase 3: stream out = x + delta via float4, streaming stores
// 204 floats/slice = 51 float4; an aligned float4 never crosses an m-wrap.
// Root region floats 132..155 = float4 indices 33..38 of the slice.
// ---------------------------------------------------------------------------
__global__ __launch_bounds__(256) void fused_kernel(
    const float* __restrict__ x, float* __restrict__ out,
    const float* __restrict__ lambda_fuse, const float* __restrict__ tag_gate)
{
    const int slice0 = blockIdx.x * SL;         // 32 | 2400 -> block within one n
    const int n      = slice0 / (Cc * Tt);
    const int tid    = threadIdx.x;

    __shared__ float A_s[144];                  // rows 48B-aligned
    __shared__ float r_s[SL][12];
    __shared__ float delta_s[SL][12];
    __shared__ float coef_s;

    if (tid < 144) A_s[tid] = g_A[n * 144 + tid];
    if (tid == 0) coef_s = tanhf(tag_gate[0]) * lambda_fuse[0];

    const float4* x4base = (const float4*)x + (size_t)slice0 * 51;

    // Phase 1: 96 items (sidx, q), q=0..2 covering 12 root floats as float4
    if (tid < SL * 3) {
        const int sidx = tid / 3, q = tid - sidx * 3;
        const float4 a = x4base[sidx * 51 + 33 + q];
        const float4 bq = x4base[sidx * 51 + 36 + q];
        float4 r;
        r.x = 0.5f * (a.x + bq.x);
        r.y = 0.5f * (a.y + bq.y);
        r.z = 0.5f * (a.z + bq.z);
        r.w = 0.5f * (a.w + bq.w);
        *(float4*)&r_s[sidx][q * 4] = r;
    }
    __syncthreads();

    // Phase 2: 384 items: delta[sidx][m] = coef*(dot(A[m,:], r[sidx]) - r[sidx][m])
    for (int it = tid; it < SL * 12; it += 256) {
        const int sidx = it / 12, m = it - sidx * 12;
        const float4 a0 = *(const float4*)&A_s[m * 12 + 0];
        const float4 a1 = *(const float4*)&A_s[m * 12 + 4];
        const float4 a2 = *(const float4*)&A_s[m * 12 + 8];
        const float4 r0 = *(const float4*)&r_s[sidx][0];
        const float4 r1 = *(const float4*)&r_s[sidx][4];
        const float4 r2 = *(const float4*)&r_s[sidx][8];
        float agg = a0.x * r0.x + a0.y * r0.y + a0.z * r0.z + a0.w * r0.w
                  + a1.x * r1.x + a1.y * r1.y + a1.z * r1.z + a1.w * r1.w
                  + a2.x * r2.x + a2.y * r2.y + a2.z * r2.z + a2.w * r2.w;
        delta_s[sidx][m] = coef_s * (agg - r_s[sidx][m]);
    }
    __syncthreads();

    // Phase 3: stream
    float4* o4 = (float4*)out + (size_t)slice0 * 51;
#pragma unroll 4
    for (int k = tid; k < SL * 51; k += 256) {
        const int sidx = k / 51, r = k - sidx * 51;
        const float4 d = *(const float4*)&delta_s[sidx][(r % 3) * 4];
        float4 xv = x4base[k];
        xv.x += d.x; xv.y += d.y; xv.z += d.z; xv.w += d.w;
        __stcs(&o4[k], xv);
    }
}

// ---------------------------------------------------------------------------
extern "C" void kernel_launch(void* const* d_in, const int* in_sizes, int n_in,
                              void* d_out, int out_size)
{
    const float* x            = (const float*)d_in[0];
    const float* alpha_logits = (const float*)d_in[1];
    const float* lambda_fuse  = (const float*)d_in[2];
    const float* tag_gate     = (const float*)d_in[3];
    float* out = (float*)d_out;

    stats1_kernel<<<Nn * NCHUNK, 256>>>(x);
    graph_kernel<<<Nn, 64>>>(alpha_logits);
    fused_kernel<<<SLICES / SL, 256>>>(x, out, lambda_fuse, tag_gate);
}

// round 5
// speedup vs baseline: 1.5913x; 1.0261x over previous
#include <cuda_runtime.h>
#include <cuda_bf16.h>
#include <math.h>

// Problem dims (fixed by the dataset)
#define Nn 64
#define Cc 8
#define Tt 300
#define Vv 17
#define Mm 12
#define SLICES (Nn*Cc*Tt)          // 153600 (n,c,t) slices of V*M=204 floats
#define EPSF 1e-6f
#define TAUF 0.35f

#define NCHUNK 30                  // T split into 30 chunks of 10
#define CH 10                      // t per chunk
#define SL 48                      // slices per block in fused kernel (48 | 2400)

// Scratch (device globals — no allocation allowed)
__device__ float g_A[Nn*Mm*Mm];               // per-sample 12x12 adjacency
__device__ float g_part[Nn*NCHUNK*48];        // partials: 12 s + 36 pos per (n,chunk)

// packed f32x2 add (bit-identical to scalar FADD.rn)
__device__ __forceinline__ float4 f4add(float4 a, float4 b) {
    union { float4 f; unsigned long long u[2]; } A, B, O;
    A.f = a; B.f = b;
    asm("add.rn.f32x2 %0, %1, %2;" : "=l"(O.u[0]) : "l"(A.u[0]), "l"(B.u[0]));
    asm("add.rn.f32x2 %0, %1, %2;" : "=l"(O.u[1]) : "l"(A.u[1]), "l"(B.u[1]));
    return O.f;
}

// ---------------------------------------------------------------------------
// Kernel 1: partial reductions, fully vectorized. grid = 1920, 256 threads.
// One (n, 10-t chunk) per block.
// s-slab: 10*204 = 2040 floats = 510 float4 (contiguous). float4 q covers
// m = 4*(q%3) + c. Thread loads q=tid and q=tid+255 (same phase, 255%3==0).
// pos: 6 float4 per (t,d) covering floats 132..155 (joints 11,12).
// ---------------------------------------------------------------------------
__global__ __launch_bounds__(256) void stats1_kernel(const float* __restrict__ x)
{
    const int b   = blockIdx.x;
    const int n   = b / NCHUNK, ch = b % NCHUNK;
    const int tid = threadIdx.x;
    const float* xn = x + (size_t)n * Cc * Tt * Vv * Mm;

    __shared__ float4 sred4[256];
    __shared__ float4 posq[3][CH][6];

    // ---- s partial loads: 510 float4
    {
        const float4* slab = (const float4*)(xn + 3 * Tt * Vv * Mm + ch * CH * 204);
        float4 acc = make_float4(0.f, 0.f, 0.f, 0.f);
        if (tid < 255)
            acc = f4add(slab[tid], slab[tid + 255]);
        sred4[tid] = acc;
    }

    // ---- pos loads: 180 threads, one float4 each
    if (tid < 180) {
        const int d = tid / 60, rem = tid % 60;
        const int tl = rem / 6, q = rem % 6;
        const float4* x4n = (const float4*)(xn + (size_t)d * Tt * Vv * Mm);
        posq[d][tl][q] = x4n[(ch * CH + tl) * 51 + 33 + q];
    }
    __syncthreads();

    // ---- s reduce stage 1: 51 | 3 keeps phases
    if (tid < 51) {
        float4 a = f4add(sred4[tid], sred4[tid + 51]);
        float4 c = f4add(sred4[tid + 102], sred4[tid + 153]);
        sred4[tid] = f4add(f4add(a, c), sred4[tid + 204]);
    }
    __syncthreads();

    if (tid < 12) {
        // m = 4p + c
        const int p = tid / 4, c = tid % 4;
        float t = 0.f;
#pragma unroll
        for (int j = 0; j < 17; j++)
            t += ((const float*)&sred4[p + 3 * j])[c];
        g_part[b * 48 + tid] = t;
    } else if (tid < 48) {
        const int d = (tid - 12) / 12, m = (tid - 12) % 12;
        const int q1 = m / 4, c = m % 4;       // joint 11: float m; joint 12: float m+12 -> q1+3
        const float* pf = (const float*)&posq[d][0][0];
        float t = 0.f;
#pragma unroll
        for (int tl = 0; tl < CH; tl++)
            t += pf[(tl * 6 + q1) * 4 + c] + pf[(tl * 6 + q1 + 3) * 4 + c];
        g_part[b * 48 + tid] = t;
    }
}

// ---------------------------------------------------------------------------
// Kernel 2: reduce partials + build A. grid = 64 blocks, 64 threads.
// ---------------------------------------------------------------------------
__global__ __launch_bounds__(64) void graph_kernel(const float* __restrict__ alpha_logits)
{
    const int n = blockIdx.x, tid = threadIdx.x;
    __shared__ float s[12], pos[3][12], p[12], alpha[4], wsh;

    if (tid < 48) {
        float t = 0.f;
#pragma unroll
        for (int ch = 0; ch < NCHUNK; ch++)
            t += g_part[(n * NCHUNK + ch) * 48 + tid];
        if (tid < 12) s[tid] = t * (1.0f / (Tt * Vv));
        else {
            const int d = (tid - 12) / 12, m = (tid - 12) % 12;
            pos[d][m] = t * (0.5f / Tt);
        }
    }
    __syncthreads();

    if (tid == 0) {
        float mx = alpha_logits[0];
        for (int k = 1; k < 4; k++) mx = fmaxf(mx, alpha_logits[k]);
        float e[4], se = 0.f;
        for (int k = 0; k < 4; k++) { e[k] = expf(alpha_logits[k] - mx); se += e[k]; }
        for (int k = 0; k < 4; k++) alpha[k] = e[k] / se;

        float smax = -1e30f;
        for (int m = 0; m < 12; m++) smax = fmaxf(smax, s[m] * (1.0f / TAUF));
        float ps = 0.f;
        for (int m = 0; m < 12; m++) { p[m] = expf(s[m] * (1.0f / TAUF) - smax); ps += p[m]; }
        float pmax = 0.f;
        for (int m = 0; m < 12; m++) { p[m] /= ps; pmax = fmaxf(pmax, p[m]); }

        float w = (pmax - 1.0f / 12.0f) / (1.0f - 1.0f / 12.0f + EPSF);
        wsh = fminf(fmaxf(w, 0.0f), 1.0f);
    }
    __syncthreads();

    if (tid < 12) {
        const int i = tid;
        float dist[12];
        for (int j = 0; j < 12; j++) {
            float dx = pos[0][i] - pos[0][j];
            float dy = pos[1][i] - pos[1][j];
            float dz = pos[2][i] - pos[2][j];
            dist[j] = dx * dx + dy * dy + dz * dz;   // monotone in euclid
        }
        // 5-NN selection order; ties -> lowest index (matches jax top_k)
        int rank[12];
        bool used[12];
        for (int j = 0; j < 12; j++) { rank[j] = 9; used[j] = false; }
        for (int r = 0; r < 5; r++) {
            float best = 3.4e38f; int bj = 0;
            for (int j = 0; j < 12; j++)
                if (!used[j] && dist[j] < best) { best = dist[j]; bj = j; }
            used[bj] = true; rank[bj] = r;
        }
        // sym_norm(A_k) = A_k / (k+1+eps): row sums are exactly k+1
        float invk[4];
        for (int kidx = 0; kidx < 4; kidx++) {
            float ds = rsqrtf((float)(kidx + 3) + EPSF);
            invk[kidx] = alpha[kidx] * ds * ds;
        }
        const float diagsum = invk[0] + invk[1] + invk[2] + invk[3];
        float rankw[5];
        rankw[0] = diagsum;
        rankw[1] = diagsum;
        rankw[2] = invk[1] + invk[2] + invk[3];
        rankw[3] = invk[2] + invk[3];
        rankw[4] = invk[3];

        const float w = wsh;
        const float disb_i = rsqrtf(12.0f * p[i] + 2.0f + EPSF);
        float* Arow = g_A + (n * 144 + i * 12);
        for (int j = 0; j < 12; j++) {
            float aknn = (rank[j] < 5 ? rankw[rank[j]] : 0.0f)
                       + (i == j ? diagsum : 0.0f);
            float disb_j = rsqrtf(12.0f * p[j] + 2.0f + EPSF);
            float aball = disb_i * disb_j * (p[i] + p[j] + (i == j ? 1.0f : 0.0f));
            Arow[j] = w * aball + (1.0f - w) * aknn;
        }
    }
}

// ---------------------------------------------------------------------------
// Kernel 3 (fused): 48 slices per block, 3200 blocks.
//  Phase 1: stage r[sidx][m] via float4 (288 LDG.128/block)
//  Phase 2: delta = coef*(A·r - r) from shared
//  Phase 3: stream out = x + delta. Incremental index math: 51%3==0 so the
//           delta float4 index is (k/51, k%3); with k-stride 256 these advance
//           by +5 / +1(mod 3) per iteration. No division in the loop.
// ---------------------------------------------------------------------------
__global__ __launch_bounds__(256) void fused_kernel(
    const float* __restrict__ x, float* __restrict__ out,
    const float* __restrict__ lambda_fuse, const float* __restrict__ tag_gate)
{
    const int slice0 = blockIdx.x * SL;         // 48 | 2400 -> block within one n
    const int n      = slice0 / (Cc * Tt);
    const int tid    = threadIdx.x;

    __shared__ float A_s[144];
    __shared__ float r_s[SL][12];
    __shared__ float delta_s[SL][12];           // 48B rows, float4-aligned
    __shared__ float coef_s;

    if (tid < 144) A_s[tid] = g_A[n * 144 + tid];
    if (tid == 0) coef_s = tanhf(tag_gate[0]) * lambda_fuse[0];

    const float4* x4base = (const float4*)x + (size_t)slice0 * 51;

    // Phase 1: 144 threads, 2 LDG.128 each (root floats = float4 33..38)
    if (tid < SL * 3) {
        const int sidx = tid / 3, q = tid - sidx * 3;
        const float4 a  = x4base[sidx * 51 + 33 + q];
        const float4 bq = x4base[sidx * 51 + 36 + q];
        float4 r;
        r.x = 0.5f * (a.x + bq.x);
        r.y = 0.5f * (a.y + bq.y);
        r.z = 0.5f * (a.z + bq.z);
        r.w = 0.5f * (a.w + bq.w);
        *(float4*)&r_s[sidx][q * 4] = r;
    }
    __syncthreads();

    // Phase 2: 576 items
    for (int it = tid; it < SL * 12; it += 256) {
        const int sidx = it / 12, m = it - sidx * 12;
        const float4 a0 = *(const float4*)&A_s[m * 12 + 0];
        const float4 a1 = *(const float4*)&A_s[m * 12 + 4];
        const float4 a2 = *(const float4*)&A_s[m * 12 + 8];
        const float4 r0 = *(const float4*)&r_s[sidx][0];
        const float4 r1 = *(const float4*)&r_s[sidx][4];
        const float4 r2 = *(const float4*)&r_s[sidx][8];
        float agg = a0.x * r0.x + a0.y * r0.y + a0.z * r0.z + a0.w * r0.w
                  + a1.x * r1.x + a1.y * r1.y + a1.z * r1.z + a1.w * r1.w
                  + a2.x * r2.x + a2.y * r2.y + a2.z * r2.z + a2.w * r2.w;
        delta_s[sidx][m] = coef_s * (agg - r_s[sidx][m]);
    }
    __syncthreads();

    // Phase 3: stream SL*51 = 2448 float4 = 9*256 + 144
    float4* o4 = (float4*)out + (size_t)slice0 * 51;
    const char* dmem = (const char*)delta_s;

    int k    = tid;
    int r    = tid % 51;
    int rm3  = r % 3;
    int doff = (tid / 51) * 48;

#pragma unroll
    for (int it = 0; it < 9; ++it) {
        const float4 d  = *(const float4*)(dmem + (doff + rm3 * 16));
        const float4 xv = x4base[k];
        __stcs(&o4[k], f4add(xv, d));
        k += 256;
        doff += 240;
        rm3 = (rm3 == 2) ? 0 : rm3 + 1;
        r += 1;
        if (r == 51) { r = 0; doff += 48; }
    }
    if (tid < 144) {
        const float4 d  = *(const float4*)(dmem + (doff + rm3 * 16));
        const float4 xv = x4base[k];
        __stcs(&o4[k], f4add(xv, d));
    }
}

// ---------------------------------------------------------------------------
extern "C" void kernel_launch(void* const* d_in, const int* in_sizes, int n_in,
                              void* d_out, int out_size)
{
    const float* x            = (const float*)d_in[0];
    const float* alpha_logits = (const float*)d_in[1];
    const float* lambda_fuse  = (const float*)d_in[2];
    const float* tag_gate     = (const float*)d_in[3];
    float* out = (float*)d_out;

    stats1_kernel<<<Nn * NCHUNK, 256>>>(x);
    graph_kernel<<<Nn, 64>>>(alpha_logits);
    fused_kernel<<<SLICES / SL, 256>>>(x, out, lambda_fuse, tag_gate);
}